// round 12
// baseline (speedup 1.0000x reference)
#include <cuda_runtime.h>
#include <cuda_fp16.h>

#define N_MAX   (384*384)     // 147456 pixels
#define A_FEAT  32            // features per pixel
#define K_NBR   48            // neighbors per pixel
#define EPSV    1e-9f

// Row-major fp16 feature table UU[N][32] (64B rows, 128B-aligned base).
__device__ __align__(128) __half g_UUh[N_MAX * A_FEAT];

// ---------------------------------------------------------------------------
// Kernel 1: transpose + compress input1 [32, N] fp32 -> g_UUh [N, 32] fp16
// ---------------------------------------------------------------------------
__global__ void transpose_kernel(const float* __restrict__ in, int N) {
    __shared__ float tile[32][33];
    const int n0 = blockIdx.x * 32;
    const int tx = threadIdx.x;      // 0..31
    const int ty = threadIdx.y;      // 0..7
#pragma unroll
    for (int i = 0; i < 32; i += 8) {
        tile[ty + i][tx] = in[(size_t)(ty + i) * N + n0 + tx];
    }
    __syncthreads();
    __half2* __restrict__ out2 = reinterpret_cast<__half2*>(g_UUh);
    const int id = ty * 32 + tx;          // 0..255
    const int c  = id & 15;               // half2 column 0..15
    const int r0 = id >> 4;               // 0..15
#pragma unroll
    for (int rr = 0; rr < 2; rr++) {
        const int r = r0 + rr * 16;
        out2[(size_t)(n0 + r) * 16 + c] =
            __floats2half2_rn(tile[2 * c][r], tile[2 * c + 1][r]);
    }
}

// squared distance over this lane's 8 features (fp16x2, two depth-2 chains)
__device__ __forceinline__ float sqdist8(
        const uint4 r, const __half2 uh0, const __half2 uh1,
        const __half2 uh2, const __half2 uh3) {
    const __half2 vh0 = *reinterpret_cast<const __half2*>(&r.x);
    const __half2 vh1 = *reinterpret_cast<const __half2*>(&r.y);
    const __half2 vh2 = *reinterpret_cast<const __half2*>(&r.z);
    const __half2 vh3 = *reinterpret_cast<const __half2*>(&r.w);
    const __half2 d0 = __hsub2(uh0, vh0);
    const __half2 d1 = __hsub2(uh1, vh1);
    const __half2 d2 = __hsub2(uh2, vh2);
    const __half2 d3 = __hsub2(uh3, vh3);
    const __half2 qa = __hfma2(d1, d1, __hmul2(d0, d0));
    const __half2 qb = __hfma2(d3, d3, __hmul2(d2, d2));
    const __half2 q  = __hadd2(qa, qb);
    return __low2float(q) + __high2float(q);
}

// ---------------------------------------------------------------------------
// Kernel 2: 4 lanes per pixel (8 pixels/warp). Lane owns 16B (8 features).
// Gather: 4x LDG.128 per step (each covering 8 random rows = 8 lines, MLP=4).
// Offsets pre-shifted into padded smem; one broadcast LDS.128 per step.
// Softmax without max-subtraction (D<=0 always). 7 blocks/SM target.
// ---------------------------------------------------------------------------
__global__ void __launch_bounds__(256, 7) dist_softmax_kernel(
        const int* __restrict__ idx,       // [N, 48] int32
        float* __restrict__ out, int N) {
    const int gtid   = blockIdx.x * blockDim.x + threadIdx.x;
    const int warpId = gtid >> 5;
    const int lane   = threadIdx.x & 31;
    const int p      = lane >> 2;        // pixel within warp 0..7
    const int gl     = lane & 3;         // lane within 4-lane group
    const int j      = warpId * 8 + p;   // pixel
    const int wIdx   = threadIdx.x >> 5; // warp within block
    if (j >= N) return;

    __shared__ int   offs[8][8][52];     // [warp][pixel][48 padded to 52]
    __shared__ float stage[8][8][52];
    __shared__ float invs[8][8];

    const char* __restrict__ gUU = reinterpret_cast<const char*>(g_UUh);
    const char* __restrict__ gUUlane = gUU + (gl << 4);   // lane's 16B slot

    // own 8 features as 4x half2
    __half2 uh0, uh1, uh2, uh3;
    {
        const uint4 uraw = *reinterpret_cast<const uint4*>(
            gUU + ((size_t)(unsigned)j << 6) + (gl << 4));
        uh0 = *reinterpret_cast<const __half2*>(&uraw.x);
        uh1 = *reinterpret_cast<const __half2*>(&uraw.y);
        uh2 = *reinterpret_cast<const __half2*>(&uraw.z);
        uh3 = *reinterpret_cast<const __half2*>(&uraw.w);
    }

    // preload all 48 offsets into smem (indices guaranteed in [0,N))
    {
        const int4* __restrict__ idx4 =
            reinterpret_cast<const int4*>(idx + (size_t)j * K_NBR);
#pragma unroll
        for (int q = 0; q < 3; q++) {
            int4 v = idx4[4 * q + gl];
            v.x <<= 6; v.y <<= 6; v.z <<= 6; v.w <<= 6;   // row byte offsets
            *reinterpret_cast<int4*>(&offs[wIdx][p][16 * q + 4 * gl]) = v;
        }
    }
    __syncwarp();

    const bool b0 = (gl & 1) != 0;
    const bool b1 = (gl & 2) != 0;

    float ssum = 0.0f;
#pragma unroll
    for (int t = 0; t < 12; t++) {
        // one broadcast LDS.128: the 4 offsets of this step
        const int4 o = *reinterpret_cast<const int4*>(&offs[wIdx][p][4 * t]);
        const uint4 r0 = *reinterpret_cast<const uint4*>(gUUlane + (size_t)(unsigned)o.x);
        const uint4 r1 = *reinterpret_cast<const uint4*>(gUUlane + (size_t)(unsigned)o.y);
        const uint4 r2 = *reinterpret_cast<const uint4*>(gUUlane + (size_t)(unsigned)o.z);
        const uint4 r3 = *reinterpret_cast<const uint4*>(gUUlane + (size_t)(unsigned)o.w);

        const float a0 = sqdist8(r0, uh0, uh1, uh2, uh3);
        const float a1 = sqdist8(r1, uh0, uh1, uh2, uh3);
        const float a2 = sqdist8(r2, uh0, uh1, uh2, uh3);
        const float a3 = sqdist8(r3, uh0, uh1, uh2, uh3);

        // 3-shfl multi-value butterfly (width 4): lane gl keeps s = gl
        const float u0 = b0 ? a1 : a0;
        const float s0 = b0 ? a0 : a1;
        const float u1 = b0 ? a3 : a2;
        const float s1 = b0 ? a2 : a3;
        const float m0 = u0 + __shfl_xor_sync(0xffffffffu, s0, 1, 4);
        const float m1 = u1 + __shfl_xor_sync(0xffffffffu, s1, 1, 4);
        const float uu = b1 ? m1 : m0;
        const float sv = b1 ? m0 : m1;
        const float Dt = uu + __shfl_xor_sync(0xffffffffu, sv, 2, 4);

        // e = exp(-sqrt(mean+eps))  (no max-sub: arg is in (-10, 0])
        const float e = __expf(-sqrtf(fmaf(Dt, 1.0f / 32.0f, EPSV)));
        ssum += e;
        stage[wIdx][p][4 * t + gl] = e;     // neighbor 4t+gl
    }

    // group sum over 4 lanes
    ssum += __shfl_xor_sync(0xffffffffu, ssum, 1, 4);
    ssum += __shfl_xor_sync(0xffffffffu, ssum, 2, 4);
    if (gl == 0) invs[wIdx][p] = 1.0f / ssum;
    __syncwarp();

    // per-warp contiguous 1536B output: lane writes floats [lane*12, lane*12+12)
    {
        float* __restrict__ owarp = out + (size_t)warpId * 8 * K_NBR;
        const int pr = lane >> 2;                 // source pixel row
        const int kb = 12 * (lane & 3);           // base column
        const float iv = invs[wIdx][pr];
#pragma unroll
        for (int i = 0; i < 3; i++) {
            float4 v = *reinterpret_cast<const float4*>(
                &stage[wIdx][pr][kb + 4 * i]);
            v.x *= iv; v.y *= iv; v.z *= iv; v.w *= iv;
            *reinterpret_cast<float4*>(owarp + lane * 12 + 4 * i) = v;
        }
    }
}

// ---------------------------------------------------------------------------
extern "C" void kernel_launch(void* const* d_in, const int* in_sizes, int n_in,
                              void* d_out, int out_size) {
    const float* input1 = (const float*)d_in[0];   // [32, N] fp32
    const int*   input2 = (const int*)d_in[1];     // [N, 48] int32 (JAX x64 off)
    float*       out    = (float*)d_out;           // [N, 48] fp32

    const int N = in_sizes[0] / A_FEAT;   // 147456

    {
        dim3 blk(32, 8);
        dim3 grd(N / 32);
        transpose_kernel<<<grd, blk>>>(input1, N);
    }
    {
        const int threads = 256;
        const long long total = (long long)N * 4;   // 4 lanes per pixel
        const int blocks = (int)((total + threads - 1) / threads);
        dist_softmax_kernel<<<blocks, threads>>>(input2, out, N);
    }
}

// round 13
// speedup vs baseline: 1.3860x; 1.3860x over previous
#include <cuda_runtime.h>
#include <cuda_fp16.h>

#define N_MAX   (384*384)     // 147456 pixels
#define A_FEAT  32            // features per pixel
#define K_NBR   48            // neighbors per pixel
#define EPSV    1e-9f

// Row-major fp16 feature table UU[N][32] (64B rows, 128B-aligned base).
__device__ __align__(128) __half g_UUh[N_MAX * A_FEAT];

// ---------------------------------------------------------------------------
// Kernel 1: transpose + compress input1 [32, N] fp32 -> g_UUh [N, 32] fp16
// ---------------------------------------------------------------------------
__global__ void transpose_kernel(const float* __restrict__ in, int N) {
    __shared__ float tile[32][33];
    const int n0 = blockIdx.x * 32;
    const int tx = threadIdx.x;      // 0..31
    const int ty = threadIdx.y;      // 0..7
#pragma unroll
    for (int i = 0; i < 32; i += 8) {
        tile[ty + i][tx] = in[(size_t)(ty + i) * N + n0 + tx];
    }
    __syncthreads();
    __half2* __restrict__ out2 = reinterpret_cast<__half2*>(g_UUh);
    const int id = ty * 32 + tx;          // 0..255
    const int c  = id & 15;               // half2 column 0..15
    const int r0 = id >> 4;               // 0..15
#pragma unroll
    for (int rr = 0; rr < 2; rr++) {
        const int r = r0 + rr * 16;
        out2[(size_t)(n0 + r) * 16 + c] =
            __floats2half2_rn(tile[2 * c][r], tile[2 * c + 1][r]);
    }
}

// squared distance over this lane's 8 features (fp16x2, two depth-2 chains)
__device__ __forceinline__ float sqdist8(
        const uint4 r, const __half2 uh0, const __half2 uh1,
        const __half2 uh2, const __half2 uh3) {
    const __half2 vh0 = *reinterpret_cast<const __half2*>(&r.x);
    const __half2 vh1 = *reinterpret_cast<const __half2*>(&r.y);
    const __half2 vh2 = *reinterpret_cast<const __half2*>(&r.z);
    const __half2 vh3 = *reinterpret_cast<const __half2*>(&r.w);
    const __half2 d0 = __hsub2(uh0, vh0);
    const __half2 d1 = __hsub2(uh1, vh1);
    const __half2 d2 = __hsub2(uh2, vh2);
    const __half2 d3 = __hsub2(uh3, vh3);
    const __half2 qa = __hfma2(d1, d1, __hmul2(d0, d0));
    const __half2 qb = __hfma2(d3, d3, __hmul2(d2, d2));
    const __half2 q  = __hadd2(qa, qb);
    return __low2float(q) + __high2float(q);
}

// ---------------------------------------------------------------------------
// Kernel 2: 4 lanes per pixel (8 pixels/warp). Lane owns 16B (8 features).
// Gather: 4x LDG.128 per step (each covering 8 random rows = 8 lines, MLP=4).
// Offsets pre-shifted into padded smem; one broadcast LDS.128 per step.
// Softmax without max-subtraction (D<=0 always). 128-thread blocks,
// 12 blocks/SM (same 48-warp residency as R10, finer CLC granularity).
// ---------------------------------------------------------------------------
__global__ void __launch_bounds__(128, 12) dist_softmax_kernel(
        const int* __restrict__ idx,       // [N, 48] int32
        float* __restrict__ out, int N) {
    const int gtid   = blockIdx.x * blockDim.x + threadIdx.x;
    const int warpId = gtid >> 5;
    const int lane   = threadIdx.x & 31;
    const int p      = lane >> 2;        // pixel within warp 0..7
    const int gl     = lane & 3;         // lane within 4-lane group
    const int j      = warpId * 8 + p;   // pixel
    const int wIdx   = threadIdx.x >> 5; // warp within block (0..3)
    if (j >= N) return;

    __shared__ int   offs[4][8][52];     // [warp][pixel][48 padded to 52]
    __shared__ float stage[4][8][52];
    __shared__ float invs[4][8];

    const char* __restrict__ gUU = reinterpret_cast<const char*>(g_UUh);
    const char* __restrict__ gUUlane = gUU + (gl << 4);   // lane's 16B slot

    // own 8 features as 4x half2
    __half2 uh0, uh1, uh2, uh3;
    {
        const uint4 uraw = *reinterpret_cast<const uint4*>(
            gUU + ((size_t)(unsigned)j << 6) + (gl << 4));
        uh0 = *reinterpret_cast<const __half2*>(&uraw.x);
        uh1 = *reinterpret_cast<const __half2*>(&uraw.y);
        uh2 = *reinterpret_cast<const __half2*>(&uraw.z);
        uh3 = *reinterpret_cast<const __half2*>(&uraw.w);
    }

    // preload all 48 offsets into smem (indices guaranteed in [0,N))
    {
        const int4* __restrict__ idx4 =
            reinterpret_cast<const int4*>(idx + (size_t)j * K_NBR);
#pragma unroll
        for (int q = 0; q < 3; q++) {
            int4 v = idx4[4 * q + gl];
            v.x <<= 6; v.y <<= 6; v.z <<= 6; v.w <<= 6;   // row byte offsets
            *reinterpret_cast<int4*>(&offs[wIdx][p][16 * q + 4 * gl]) = v;
        }
    }
    __syncwarp();

    const bool b0 = (gl & 1) != 0;
    const bool b1 = (gl & 2) != 0;

    float ssum = 0.0f;
#pragma unroll
    for (int t = 0; t < 12; t++) {
        // one broadcast LDS.128: the 4 offsets of this step
        const int4 o = *reinterpret_cast<const int4*>(&offs[wIdx][p][4 * t]);
        const uint4 r0 = *reinterpret_cast<const uint4*>(gUUlane + (size_t)(unsigned)o.x);
        const uint4 r1 = *reinterpret_cast<const uint4*>(gUUlane + (size_t)(unsigned)o.y);
        const uint4 r2 = *reinterpret_cast<const uint4*>(gUUlane + (size_t)(unsigned)o.z);
        const uint4 r3 = *reinterpret_cast<const uint4*>(gUUlane + (size_t)(unsigned)o.w);

        const float a0 = sqdist8(r0, uh0, uh1, uh2, uh3);
        const float a1 = sqdist8(r1, uh0, uh1, uh2, uh3);
        const float a2 = sqdist8(r2, uh0, uh1, uh2, uh3);
        const float a3 = sqdist8(r3, uh0, uh1, uh2, uh3);

        // 3-shfl multi-value butterfly (width 4): lane gl keeps s = gl
        const float u0 = b0 ? a1 : a0;
        const float s0 = b0 ? a0 : a1;
        const float u1 = b0 ? a3 : a2;
        const float s1 = b0 ? a2 : a3;
        const float m0 = u0 + __shfl_xor_sync(0xffffffffu, s0, 1, 4);
        const float m1 = u1 + __shfl_xor_sync(0xffffffffu, s1, 1, 4);
        const float uu = b1 ? m1 : m0;
        const float sv = b1 ? m0 : m1;
        const float Dt = uu + __shfl_xor_sync(0xffffffffu, sv, 2, 4);

        // e = exp(-sqrt(mean+eps))  (no max-sub: arg is in (-10, 0])
        const float e = __expf(-sqrtf(fmaf(Dt, 1.0f / 32.0f, EPSV)));
        ssum += e;
        stage[wIdx][p][4 * t + gl] = e;     // neighbor 4t+gl
    }

    // group sum over 4 lanes
    ssum += __shfl_xor_sync(0xffffffffu, ssum, 1, 4);
    ssum += __shfl_xor_sync(0xffffffffu, ssum, 2, 4);
    if (gl == 0) invs[wIdx][p] = 1.0f / ssum;
    __syncwarp();

    // per-warp contiguous 1536B output: lane writes floats [lane*12, lane*12+12)
    {
        float* __restrict__ owarp = out + (size_t)warpId * 8 * K_NBR;
        const int pr = lane >> 2;                 // source pixel row
        const int kb = 12 * (lane & 3);           // base column
        const float iv = invs[wIdx][pr];
#pragma unroll
        for (int i = 0; i < 3; i++) {
            float4 v = *reinterpret_cast<const float4*>(
                &stage[wIdx][pr][kb + 4 * i]);
            v.x *= iv; v.y *= iv; v.z *= iv; v.w *= iv;
            *reinterpret_cast<float4*>(owarp + lane * 12 + 4 * i) = v;
        }
    }
}

// ---------------------------------------------------------------------------
extern "C" void kernel_launch(void* const* d_in, const int* in_sizes, int n_in,
                              void* d_out, int out_size) {
    const float* input1 = (const float*)d_in[0];   // [32, N] fp32
    const int*   input2 = (const int*)d_in[1];     // [N, 48] int32 (JAX x64 off)
    float*       out    = (float*)d_out;           // [N, 48] fp32

    const int N = in_sizes[0] / A_FEAT;   // 147456

    {
        dim3 blk(32, 8);
        dim3 grd(N / 32);
        transpose_kernel<<<grd, blk>>>(input1, N);
    }
    {
        const int threads = 128;
        const long long total = (long long)N * 4;   // 4 lanes per pixel
        const int blocks = (int)((total + threads - 1) / threads);
        dist_softmax_kernel<<<blocks, threads>>>(input2, out, N);
    }
}

// round 14
// speedup vs baseline: 1.3943x; 1.0061x over previous
#include <cuda_runtime.h>
#include <cuda_fp16.h>

#define N_MAX   (384*384)     // 147456 pixels
#define A_FEAT  32            // features per pixel
#define K_NBR   48            // neighbors per pixel
#define EPSV    1e-9f

// Row-major fp16 feature table UU[N][32] (64B rows, 128B-aligned base).
__device__ __align__(128) __half g_UUh[N_MAX * A_FEAT];

// ---------------------------------------------------------------------------
// Kernel 1: transpose + compress input1 [32, N] fp32 -> g_UUh [N, 32] fp16.
// 64-pixel tiles (2304 blocks), odd-stride smem (conflict-free both phases).
// ---------------------------------------------------------------------------
__global__ void transpose_kernel(const float* __restrict__ in, int N) {
    __shared__ float tile[32][65];        // 64 px + 1 pad (odd stride)
    const int n0 = blockIdx.x * 64;
    const int tx = threadIdx.x;           // 0..31
    const int ty = threadIdx.y;           // 0..7
#pragma unroll
    for (int i = 0; i < 32; i += 8) {
        const float* rowp = in + (size_t)(ty + i) * N + n0;
        tile[ty + i][tx]      = rowp[tx];
        tile[ty + i][tx + 32] = rowp[tx + 32];
    }
    __syncthreads();
    __half2* __restrict__ out2 = reinterpret_cast<__half2*>(g_UUh);
    const int id = ty * 32 + tx;          // 0..255
    const int c  = id & 15;               // half2 column 0..15
    const int r0 = id >> 4;               // 0..15
#pragma unroll
    for (int rr = 0; rr < 4; rr++) {
        const int r = r0 + rr * 16;       // pixel within tile 0..63
        out2[(size_t)(n0 + r) * 16 + c] =
            __floats2half2_rn(tile[2 * c][r], tile[2 * c + 1][r]);
    }
}

// squared distance over this lane's 8 features (fp16x2, two depth-2 chains)
__device__ __forceinline__ float sqdist8(
        const uint4 r, const __half2 uh0, const __half2 uh1,
        const __half2 uh2, const __half2 uh3) {
    const __half2 vh0 = *reinterpret_cast<const __half2*>(&r.x);
    const __half2 vh1 = *reinterpret_cast<const __half2*>(&r.y);
    const __half2 vh2 = *reinterpret_cast<const __half2*>(&r.z);
    const __half2 vh3 = *reinterpret_cast<const __half2*>(&r.w);
    const __half2 d0 = __hsub2(uh0, vh0);
    const __half2 d1 = __hsub2(uh1, vh1);
    const __half2 d2 = __hsub2(uh2, vh2);
    const __half2 d3 = __hsub2(uh3, vh3);
    const __half2 qa = __hfma2(d1, d1, __hmul2(d0, d0));
    const __half2 qb = __hfma2(d3, d3, __hmul2(d2, d2));
    const __half2 q  = __hadd2(qa, qb);
    return __low2float(q) + __high2float(q);
}

// ---------------------------------------------------------------------------
// Kernel 2 (converged R10 winner): 4 lanes per pixel (8 pixels/warp), lane
// owns 16B of the 64B row. 4x LDG.128 per step (8 random rows each, MLP=4).
// Offsets pre-shifted into padded smem; one broadcast LDS.128 per step.
// Softmax without max-subtraction (D<=0 always). 6 blocks/SM.
// ---------------------------------------------------------------------------
__global__ void __launch_bounds__(256, 6) dist_softmax_kernel(
        const int* __restrict__ idx,       // [N, 48] int32
        float* __restrict__ out, int N) {
    const int gtid   = blockIdx.x * blockDim.x + threadIdx.x;
    const int warpId = gtid >> 5;
    const int lane   = threadIdx.x & 31;
    const int p      = lane >> 2;        // pixel within warp 0..7
    const int gl     = lane & 3;         // lane within 4-lane group
    const int j      = warpId * 8 + p;   // pixel
    const int wIdx   = threadIdx.x >> 5; // warp within block
    if (j >= N) return;

    __shared__ int   offs[8][8][52];     // [warp][pixel][48 padded to 52]
    __shared__ float stage[8][8][52];
    __shared__ float invs[8][8];

    const char* __restrict__ gUU = reinterpret_cast<const char*>(g_UUh);
    const char* __restrict__ gUUlane = gUU + (gl << 4);   // lane's 16B slot

    // own 8 features as 4x half2
    __half2 uh0, uh1, uh2, uh3;
    {
        const uint4 uraw = *reinterpret_cast<const uint4*>(
            gUU + ((size_t)(unsigned)j << 6) + (gl << 4));
        uh0 = *reinterpret_cast<const __half2*>(&uraw.x);
        uh1 = *reinterpret_cast<const __half2*>(&uraw.y);
        uh2 = *reinterpret_cast<const __half2*>(&uraw.z);
        uh3 = *reinterpret_cast<const __half2*>(&uraw.w);
    }

    // preload all 48 offsets into smem (indices guaranteed in [0,N))
    {
        const int4* __restrict__ idx4 =
            reinterpret_cast<const int4*>(idx + (size_t)j * K_NBR);
#pragma unroll
        for (int q = 0; q < 3; q++) {
            int4 v = idx4[4 * q + gl];
            v.x <<= 6; v.y <<= 6; v.z <<= 6; v.w <<= 6;   // row byte offsets
            *reinterpret_cast<int4*>(&offs[wIdx][p][16 * q + 4 * gl]) = v;
        }
    }
    __syncwarp();

    const bool b0 = (gl & 1) != 0;
    const bool b1 = (gl & 2) != 0;

    float ssum = 0.0f;
#pragma unroll
    for (int t = 0; t < 12; t++) {
        // one broadcast LDS.128: the 4 offsets of this step
        const int4 o = *reinterpret_cast<const int4*>(&offs[wIdx][p][4 * t]);
        const uint4 r0 = *reinterpret_cast<const uint4*>(gUUlane + (size_t)(unsigned)o.x);
        const uint4 r1 = *reinterpret_cast<const uint4*>(gUUlane + (size_t)(unsigned)o.y);
        const uint4 r2 = *reinterpret_cast<const uint4*>(gUUlane + (size_t)(unsigned)o.z);
        const uint4 r3 = *reinterpret_cast<const uint4*>(gUUlane + (size_t)(unsigned)o.w);

        const float a0 = sqdist8(r0, uh0, uh1, uh2, uh3);
        const float a1 = sqdist8(r1, uh0, uh1, uh2, uh3);
        const float a2 = sqdist8(r2, uh0, uh1, uh2, uh3);
        const float a3 = sqdist8(r3, uh0, uh1, uh2, uh3);

        // 3-shfl multi-value butterfly (width 4): lane gl keeps s = gl
        const float u0 = b0 ? a1 : a0;
        const float s0 = b0 ? a0 : a1;
        const float u1 = b0 ? a3 : a2;
        const float s1 = b0 ? a2 : a3;
        const float m0 = u0 + __shfl_xor_sync(0xffffffffu, s0, 1, 4);
        const float m1 = u1 + __shfl_xor_sync(0xffffffffu, s1, 1, 4);
        const float uu = b1 ? m1 : m0;
        const float sv = b1 ? m0 : m1;
        const float Dt = uu + __shfl_xor_sync(0xffffffffu, sv, 2, 4);

        // e = exp(-sqrt(mean+eps))  (no max-sub: arg is in (-10, 0])
        const float e = __expf(-sqrtf(fmaf(Dt, 1.0f / 32.0f, EPSV)));
        ssum += e;
        stage[wIdx][p][4 * t + gl] = e;     // neighbor 4t+gl
    }

    // group sum over 4 lanes
    ssum += __shfl_xor_sync(0xffffffffu, ssum, 1, 4);
    ssum += __shfl_xor_sync(0xffffffffu, ssum, 2, 4);
    if (gl == 0) invs[wIdx][p] = 1.0f / ssum;
    __syncwarp();

    // per-warp contiguous 1536B output: lane writes floats [lane*12, lane*12+12)
    {
        float* __restrict__ owarp = out + (size_t)warpId * 8 * K_NBR;
        const int pr = lane >> 2;                 // source pixel row
        const int kb = 12 * (lane & 3);           // base column
        const float iv = invs[wIdx][pr];
#pragma unroll
        for (int i = 0; i < 3; i++) {
            float4 v = *reinterpret_cast<const float4*>(
                &stage[wIdx][pr][kb + 4 * i]);
            v.x *= iv; v.y *= iv; v.z *= iv; v.w *= iv;
            *reinterpret_cast<float4*>(owarp + lane * 12 + 4 * i) = v;
        }
    }
}

// ---------------------------------------------------------------------------
extern "C" void kernel_launch(void* const* d_in, const int* in_sizes, int n_in,
                              void* d_out, int out_size) {
    const float* input1 = (const float*)d_in[0];   // [32, N] fp32
    const int*   input2 = (const int*)d_in[1];     // [N, 48] int32 (JAX x64 off)
    float*       out    = (float*)d_out;           // [N, 48] fp32

    const int N = in_sizes[0] / A_FEAT;   // 147456

    {
        dim3 blk(32, 8);
        dim3 grd(N / 64);                  // 64-pixel tiles
        transpose_kernel<<<grd, blk>>>(input1, N);
    }
    {
        const int threads = 256;
        const long long total = (long long)N * 4;   // 4 lanes per pixel
        const int blocks = (int)((total + threads - 1) / threads);
        dist_softmax_kernel<<<blocks, threads>>>(input2, out, N);
    }
}

// round 15
// speedup vs baseline: 1.4561x; 1.0443x over previous
#include <cuda_runtime.h>
#include <cuda_fp16.h>

#define N_MAX   (384*384)     // 147456 pixels
#define A_FEAT  32            // features per pixel
#define K_NBR   48            // neighbors per pixel
#define EPSV    1e-9f

// Row-major fp16 feature table UU[N][32] (64B rows, 128B-aligned base).
__device__ __align__(128) __half g_UUh[N_MAX * A_FEAT];

// ---------------------------------------------------------------------------
// Kernel 1: transpose + compress input1 [32, N] fp32 -> g_UUh [N, 32] fp16.
// 64-pixel tiles (2304 blocks), odd-stride smem (conflict-free both phases).
// ---------------------------------------------------------------------------
__global__ void transpose_kernel(const float* __restrict__ in, int N) {
    __shared__ float tile[32][65];        // 64 px + 1 pad (odd stride)
    const int n0 = blockIdx.x * 64;
    const int tx = threadIdx.x;           // 0..31
    const int ty = threadIdx.y;           // 0..7
#pragma unroll
    for (int i = 0; i < 32; i += 8) {
        const float* rowp = in + (size_t)(ty + i) * N + n0;
        tile[ty + i][tx]      = rowp[tx];
        tile[ty + i][tx + 32] = rowp[tx + 32];
    }
    __syncthreads();
    __half2* __restrict__ out2 = reinterpret_cast<__half2*>(g_UUh);
    const int id = ty * 32 + tx;          // 0..255
    const int c  = id & 15;               // half2 column 0..15
    const int r0 = id >> 4;               // 0..15
#pragma unroll
    for (int rr = 0; rr < 4; rr++) {
        const int r = r0 + rr * 16;       // pixel within tile 0..63
        out2[(size_t)(n0 + r) * 16 + c] =
            __floats2half2_rn(tile[2 * c][r], tile[2 * c + 1][r]);
    }
}

// squared distance over this lane's 8 features (fp16x2, two depth-2 chains)
__device__ __forceinline__ float sqdist8(
        const uint4 r, const __half2 uh0, const __half2 uh1,
        const __half2 uh2, const __half2 uh3) {
    const __half2 vh0 = *reinterpret_cast<const __half2*>(&r.x);
    const __half2 vh1 = *reinterpret_cast<const __half2*>(&r.y);
    const __half2 vh2 = *reinterpret_cast<const __half2*>(&r.z);
    const __half2 vh3 = *reinterpret_cast<const __half2*>(&r.w);
    const __half2 d0 = __hsub2(uh0, vh0);
    const __half2 d1 = __hsub2(uh1, vh1);
    const __half2 d2 = __hsub2(uh2, vh2);
    const __half2 d3 = __hsub2(uh3, vh3);
    const __half2 qa = __hfma2(d1, d1, __hmul2(d0, d0));
    const __half2 qb = __hfma2(d3, d3, __hmul2(d2, d2));
    const __half2 q  = __hadd2(qa, qb);
    return __low2float(q) + __high2float(q);
}

// ---------------------------------------------------------------------------
// Kernel 2 (converged R10/R14 winner) + PDL: idx preload runs BEFORE
// cudaGridDependencySynchronize() so it overlaps the transpose kernel.
// ---------------------------------------------------------------------------
__global__ void __launch_bounds__(256, 6) dist_softmax_kernel(
        const int* __restrict__ idx,       // [N, 48] int32
        float* __restrict__ out, int N) {
    const int gtid   = blockIdx.x * blockDim.x + threadIdx.x;
    const int warpId = gtid >> 5;
    const int lane   = threadIdx.x & 31;
    const int p      = lane >> 2;        // pixel within warp 0..7
    const int gl     = lane & 3;         // lane within 4-lane group
    const int j      = warpId * 8 + p;   // pixel
    const int wIdx   = threadIdx.x >> 5; // warp within block
    if (j >= N) {
        cudaGridDependencySynchronize();
        return;
    }

    __shared__ int   offs[8][8][52];     // [warp][pixel][48 padded to 52]
    __shared__ float stage[8][8][52];
    __shared__ float invs[8][8];

    const char* __restrict__ gUU = reinterpret_cast<const char*>(g_UUh);
    const char* __restrict__ gUUlane = gUU + (gl << 4);   // lane's 16B slot

    // ---- pre-dependency phase: idx preload (independent of the table) ----
    {
        const int4* __restrict__ idx4 =
            reinterpret_cast<const int4*>(idx + (size_t)j * K_NBR);
#pragma unroll
        for (int q = 0; q < 3; q++) {
            int4 v = idx4[4 * q + gl];
            v.x <<= 6; v.y <<= 6; v.z <<= 6; v.w <<= 6;   // row byte offsets
            *reinterpret_cast<int4*>(&offs[wIdx][p][16 * q + 4 * gl]) = v;
        }
    }
    __syncwarp();

    // ---- wait for the transpose kernel's table to be complete ----
    cudaGridDependencySynchronize();

    // own 8 features as 4x half2
    __half2 uh0, uh1, uh2, uh3;
    {
        const uint4 uraw = *reinterpret_cast<const uint4*>(
            gUU + ((size_t)(unsigned)j << 6) + (gl << 4));
        uh0 = *reinterpret_cast<const __half2*>(&uraw.x);
        uh1 = *reinterpret_cast<const __half2*>(&uraw.y);
        uh2 = *reinterpret_cast<const __half2*>(&uraw.z);
        uh3 = *reinterpret_cast<const __half2*>(&uraw.w);
    }

    const bool b0 = (gl & 1) != 0;
    const bool b1 = (gl & 2) != 0;

    float ssum = 0.0f;
#pragma unroll
    for (int t = 0; t < 12; t++) {
        // one broadcast LDS.128: the 4 offsets of this step
        const int4 o = *reinterpret_cast<const int4*>(&offs[wIdx][p][4 * t]);
        const uint4 r0 = *reinterpret_cast<const uint4*>(gUUlane + (size_t)(unsigned)o.x);
        const uint4 r1 = *reinterpret_cast<const uint4*>(gUUlane + (size_t)(unsigned)o.y);
        const uint4 r2 = *reinterpret_cast<const uint4*>(gUUlane + (size_t)(unsigned)o.z);
        const uint4 r3 = *reinterpret_cast<const uint4*>(gUUlane + (size_t)(unsigned)o.w);

        const float a0 = sqdist8(r0, uh0, uh1, uh2, uh3);
        const float a1 = sqdist8(r1, uh0, uh1, uh2, uh3);
        const float a2 = sqdist8(r2, uh0, uh1, uh2, uh3);
        const float a3 = sqdist8(r3, uh0, uh1, uh2, uh3);

        // 3-shfl multi-value butterfly (width 4): lane gl keeps s = gl
        const float u0 = b0 ? a1 : a0;
        const float s0 = b0 ? a0 : a1;
        const float u1 = b0 ? a3 : a2;
        const float s1 = b0 ? a2 : a3;
        const float m0 = u0 + __shfl_xor_sync(0xffffffffu, s0, 1, 4);
        const float m1 = u1 + __shfl_xor_sync(0xffffffffu, s1, 1, 4);
        const float uu = b1 ? m1 : m0;
        const float sv = b1 ? m0 : m1;
        const float Dt = uu + __shfl_xor_sync(0xffffffffu, sv, 2, 4);

        // e = exp(-sqrt(mean+eps))  (no max-sub: arg is in (-10, 0])
        const float e = __expf(-sqrtf(fmaf(Dt, 1.0f / 32.0f, EPSV)));
        ssum += e;
        stage[wIdx][p][4 * t + gl] = e;     // neighbor 4t+gl
    }

    // group sum over 4 lanes
    ssum += __shfl_xor_sync(0xffffffffu, ssum, 1, 4);
    ssum += __shfl_xor_sync(0xffffffffu, ssum, 2, 4);
    if (gl == 0) invs[wIdx][p] = 1.0f / ssum;
    __syncwarp();

    // per-warp contiguous 1536B output: lane writes floats [lane*12, lane*12+12)
    {
        float* __restrict__ owarp = out + (size_t)warpId * 8 * K_NBR;
        const int pr = lane >> 2;                 // source pixel row
        const int kb = 12 * (lane & 3);           // base column
        const float iv = invs[wIdx][pr];
#pragma unroll
        for (int i = 0; i < 3; i++) {
            float4 v = *reinterpret_cast<const float4*>(
                &stage[wIdx][pr][kb + 4 * i]);
            v.x *= iv; v.y *= iv; v.z *= iv; v.w *= iv;
            *reinterpret_cast<float4*>(owarp + lane * 12 + 4 * i) = v;
        }
    }
}

// ---------------------------------------------------------------------------
extern "C" void kernel_launch(void* const* d_in, const int* in_sizes, int n_in,
                              void* d_out, int out_size) {
    const float* input1 = (const float*)d_in[0];   // [32, N] fp32
    const int*   input2 = (const int*)d_in[1];     // [N, 48] int32 (JAX x64 off)
    float*       out    = (float*)d_out;           // [N, 48] fp32

    const int N = in_sizes[0] / A_FEAT;   // 147456

    // 1) transpose + fp16 compress
    {
        dim3 blk(32, 8);
        dim3 grd(N / 64);                  // 64-pixel tiles
        transpose_kernel<<<grd, blk>>>(input1, N);
    }
    // 2) distances + softmax, launched with Programmatic Dependent Launch so
    //    its idx-preload phase overlaps the transpose.
    {
        const int threads = 256;
        const long long total = (long long)N * 4;   // 4 lanes per pixel
        const int blocks = (int)((total + threads - 1) / threads);

        cudaLaunchConfig_t cfg = {};
        cfg.gridDim  = dim3((unsigned)blocks);
        cfg.blockDim = dim3((unsigned)threads);
        cfg.dynamicSmemBytes = 0;
        cfg.stream = 0;
        cudaLaunchAttribute attrs[1];
        attrs[0].id = cudaLaunchAttributeProgrammaticStreamSerialization;
        attrs[0].val.programmaticStreamSerializationAllowed = 1;
        cfg.attrs = attrs;
        cfg.numAttrs = 1;
        cudaLaunchKernelEx(&cfg, dist_softmax_kernel, input2, out, N);
    }
}